// round 12
// baseline (speedup 1.0000x reference)
#include <cuda_runtime.h>
#include <math.h>

#define BB 64
#define TT 512
#define DD 512
#define II 1024
#define GG 2048                 // 4*D
#define BT (BB*TT)              // 32768

// ---------------- device scratch (static: allocation-free at run time) ------
__device__ float    g_xw1[BT * GG];
__device__ float    g_xwf[BT * GG];
__device__ float    g_xwb[BT * GG];
__device__ unsigned g_h1t[BT * DD];   // layer-1 hidden, tf32 bits (GEMM A + rec)
__device__ float    g_hf [BT * DD];   // forward hidden (float, for LN)
__device__ float    g_hb [BT * DD];   // backward hidden (float, for LN)
__device__ unsigned g_hft[BT * DD];   // tf32 shadows for rec2 exchange
__device__ unsigned g_hbt[BT * DD];

// ---------------- flag-based progress barriers -------------------------------
// 64 blocks per group, 32B-strided monotonic step counters.
__device__ unsigned g_flags1[4][512];   // layer-1: 4 batch-groups x 64 blocks
__device__ unsigned g_flags2[4][512];   // layer-2: (dir,bg) 4 groups x 64 blocks

__global__ void k_zero_flags() {
    int i = blockIdx.x * blockDim.x + threadIdx.x;
    if (i < 4 * 512) {
        g_flags1[i >> 9][i & 511] = 0;
        g_flags2[i >> 9][i & 511] = 0;
    }
}

__device__ __forceinline__ void bar_signal(unsigned* flagp, unsigned val) {
    __syncthreads();                         // all h-stores of this block done
    if (threadIdx.x == 0) {
        asm volatile("fence.acq_rel.gpu;" ::: "memory");
        asm volatile("st.relaxed.gpu.global.u32 [%0], %1;"
                     :: "l"(flagp), "r"(val) : "memory");
    }
}

// 64 arrivals: one thread spins per producer flag.
// Bounded tight spin, then nanosleep backoff (hang hardening).
__device__ __forceinline__ void bar_wait64(const unsigned* flags, unsigned val) {
    if (threadIdx.x < 64) {
        const unsigned* p = flags + threadIdx.x * 8;
        unsigned v;
        int spins = 0;
        for (;;) {
            asm volatile("ld.relaxed.gpu.global.u32 %0, [%1];"
                         : "=r"(v) : "l"(p));
            if (v >= val) break;
            if (++spins > 4096) __nanosleep(64);
        }
        asm volatile("fence.acq_rel.gpu;" ::: "memory");
    }
    __syncthreads();
}

// ---------------- tf32 / mma / ldmatrix helpers ------------------------------
__device__ __forceinline__ unsigned f2tf(float f) {
    unsigned r; asm("cvt.rna.tf32.f32 %0, %1;" : "=r"(r) : "f"(f)); return r;
}

__device__ __forceinline__ void mma_tf32(float* d, const unsigned* a, const unsigned* b) {
    asm volatile("mma.sync.aligned.m16n8k8.row.col.f32.tf32.tf32.f32 "
        "{%0,%1,%2,%3}, {%4,%5,%6,%7}, {%8,%9}, {%0,%1,%2,%3};\n"
        : "+f"(d[0]), "+f"(d[1]), "+f"(d[2]), "+f"(d[3])
        : "r"(a[0]), "r"(a[1]), "r"(a[2]), "r"(a[3]), "r"(b[0]), "r"(b[1]));
}

__device__ __forceinline__ void ldsm4(unsigned& r0, unsigned& r1, unsigned& r2,
                                      unsigned& r3, const unsigned* p) {
    unsigned addr = (unsigned)__cvta_generic_to_shared(p);
    asm volatile("ldmatrix.sync.aligned.m8n8.x4.shared.b16 {%0,%1,%2,%3}, [%4];"
        : "=r"(r0), "=r"(r1), "=r"(r2), "=r"(r3) : "r"(addr));
}

__device__ __forceinline__ float sigm(float z) { return 1.f / (1.f + __expf(-z)); }

// ---------------- tf32 MMA GEMM: C[BT,GG] = A[BT,K] @ W[K,GG] + bias --------
// PRECONV: A already holds tf32 bit patterns (skip cvt on A path).
template<bool PRECONV>
__global__ void __launch_bounds__(256) k_mma_gemm(
    const float* __restrict__ A, const float* __restrict__ W,
    const float* __restrict__ bias, float* __restrict__ C, int K)
{
    __shared__ unsigned As[128][36];
    __shared__ unsigned Bs[32][136];

    const int tid  = threadIdx.x;
    const int warp = tid >> 5, lane = tid & 31;
    const int g    = lane >> 2, t = lane & 3;
    const int wm   = (warp >> 2) * 64;
    const int wn   = (warp & 3) * 32;
    const int row0 = blockIdx.y * 128, col0 = blockIdx.x * 128;

    const int a_m  = tid >> 3;
    const int a_k4 = (tid & 7) * 4;
    const int b_k  = tid >> 5;
    const int b_n4 = (tid & 31) * 4;

    float acc[4][4][4];
#pragma unroll
    for (int mi = 0; mi < 4; mi++)
#pragma unroll
        for (int ni = 0; ni < 4; ni++)
#pragma unroll
            for (int r = 0; r < 4; r++) acc[mi][ni][r] = 0.f;

    const float* Ap = A + (size_t)(row0 + a_m) * K + a_k4;
    const float* Wp = W + (size_t)b_k * GG + col0 + b_n4;

    float4 av[4], bv[4];
#pragma unroll
    for (int i = 0; i < 4; i++) av[i] = *(const float4*)(Ap + (size_t)(i * 32) * K);
#pragma unroll
    for (int i = 0; i < 4; i++) bv[i] = *(const float4*)(Wp + (size_t)(i * 8) * GG);

    for (int k0 = 0; k0 < K; k0 += 32) {
        __syncthreads();
#pragma unroll
        for (int i = 0; i < 4; i++) {
            uint4 u;
            if (PRECONV) {
                u.x = __float_as_uint(av[i].x); u.y = __float_as_uint(av[i].y);
                u.z = __float_as_uint(av[i].z); u.w = __float_as_uint(av[i].w);
            } else {
                u.x = f2tf(av[i].x); u.y = f2tf(av[i].y);
                u.z = f2tf(av[i].z); u.w = f2tf(av[i].w);
            }
            *(uint4*)&As[i * 32 + a_m][a_k4] = u;
        }
#pragma unroll
        for (int i = 0; i < 4; i++) {
            uint4 u; u.x = f2tf(bv[i].x); u.y = f2tf(bv[i].y);
                     u.z = f2tf(bv[i].z); u.w = f2tf(bv[i].w);
            *(uint4*)&Bs[i * 8 + b_k][b_n4] = u;
        }
        if (k0 + 32 < K) {
#pragma unroll
            for (int i = 0; i < 4; i++)
                av[i] = *(const float4*)(Ap + (size_t)(i * 32) * K + (k0 + 32));
#pragma unroll
            for (int i = 0; i < 4; i++)
                bv[i] = *(const float4*)(Wp + (size_t)(k0 + 32 + i * 8) * GG);
        }
        __syncthreads();

#pragma unroll
        for (int s = 0; s < 4; s++) {
            const int kk = s * 8;
            unsigned af[4][4];
#pragma unroll
            for (int mi = 0; mi < 4; mi++) {
                const int r = wm + mi * 16;
                af[mi][0] = As[r + g    ][kk + t];
                af[mi][1] = As[r + g + 8][kk + t];
                af[mi][2] = As[r + g    ][kk + t + 4];
                af[mi][3] = As[r + g + 8][kk + t + 4];
            }
            unsigned bfr[4][2];
#pragma unroll
            for (int ni = 0; ni < 4; ni++) {
                bfr[ni][0] = Bs[kk + t    ][wn + ni * 8 + g];
                bfr[ni][1] = Bs[kk + t + 4][wn + ni * 8 + g];
            }
#pragma unroll
            for (int mi = 0; mi < 4; mi++)
#pragma unroll
                for (int ni = 0; ni < 4; ni++)
                    mma_tf32(acc[mi][ni], af[mi], bfr[ni]);
        }
    }

#pragma unroll
    for (int mi = 0; mi < 4; mi++) {
        const int r0 = row0 + wm + mi * 16 + g;
#pragma unroll
        for (int ni = 0; ni < 4; ni++) {
            const int cb = col0 + wn + ni * 8 + 2 * t;
            const float b0 = bias[cb], b1 = bias[cb + 1];
            float2 v0; v0.x = acc[mi][ni][0] + b0; v0.y = acc[mi][ni][1] + b1;
            float2 v1; v1.x = acc[mi][ni][2] + b0; v1.y = acc[mi][ni][3] + b1;
            *(float2*)&C[(size_t)r0       * GG + cb] = v0;
            *(float2*)&C[(size_t)(r0 + 8) * GG + cb] = v1;
        }
    }
}

extern __shared__ unsigned dsm[];

// ---------------- persistent recurrent engine --------------------------------
// Block: NB batches x 32 gate-cols (4 gates x 8 units). 8 warps K-split (64 k).
// U slice in 64 REGISTERS per thread. 64-block groups, 2 blocks/SM from
// independent chains (latency hiding). Hs and zslab are separate regions.
#define HW 516
#define ZP 40

template<int NB>
__device__ __forceinline__ void rec_engine(
    const float* __restrict__ xw, const float* __restrict__ U,
    float* __restrict__ seqf,           // may be null (skip float store)
    unsigned* __restrict__ seqt,
    int bbase, int u0, bool rev,
    unsigned* myflag, const unsigned* gflags)
{
    unsigned (*Hs)[HW] = (unsigned(*)[HW])dsm;     // [NB][516]
    float* zslab = (float*)(dsm + NB * HW);        // [8][NB][ZP]

    const int tid  = threadIdx.x;
    const int warp = tid >> 5, lane = tid & 31;
    const int g    = lane >> 2, t = lane & 3;

    // ---- U fragments -> registers (once): 8 k-steps x 4 n-tiles x 2 -------
    unsigned bfr[8][4][2];
#pragma unroll
    for (int s = 0; s < 8; s++)
#pragma unroll
        for (int ni = 0; ni < 4; ni++) {
            const int c = ni * 8 + g;                  // 0..31
            const int gate = c >> 3, uu = c & 7;
            const size_t n = (size_t)gate * DD + u0 + uu;
            const int kg = warp * 64 + s * 8 + t;
            bfr[s][ni][0] = f2tf(U[(size_t)kg * GG + n]);
            bfr[s][ni][1] = f2tf(U[(size_t)(kg + 4) * GG + n]);
        }

    const int lt    = lane >> 3;
    const int arow  = ((lt & 1) << 3) + (lane & 7);
    const int akadd = (lt >> 1) << 2;

    // gate-phase mapping: NB*8 active threads, 1 unit each
    const int gb = tid >> 3, guu = tid & 7;
    const bool gact = (gb < NB);
    float c_reg = 0.f;

    // prefetch xw for step 0
    float xwv[4];
    if (gact) {
        const int t0 = rev ? (TT - 1) : 0;
        const size_t xrow = ((size_t)(bbase + gb) * TT + t0) * GG;
#pragma unroll
        for (int gate = 0; gate < 4; gate++)
            xwv[gate] = xw[xrow + (size_t)gate * DD + u0 + guu];
    }

    for (int st = 0; st < TT; st++) {
        const int tout  = rev ? (TT - 1 - st) : st;
        const int tprev = (st == 0) ? -1 : (rev ? tout + 1 : tout - 1);

        if (st > 0) bar_wait64(gflags, (unsigned)st);

        float acc[NB / 16][4][4];
#pragma unroll
        for (int mi = 0; mi < NB / 16; mi++)
#pragma unroll
            for (int ni = 0; ni < 4; ni++)
#pragma unroll
                for (int r = 0; r < 4; r++) acc[mi][ni][r] = 0.f;

        if (tprev >= 0) {
            // stage H[NB,512] tf32 bits -> smem (NB/2 uint4 per thread)
#pragma unroll 4
            for (int i = 0; i < NB / 2; i++) {
                const int e = i * 256 + tid;
                const int b = e >> 7, k4 = (e & 127) << 2;
                *(uint4*)&Hs[b][k4] =
                    *(const uint4*)&seqt[((size_t)(bbase + b) * TT + tprev) * DD + k4];
            }
            __syncthreads();

#pragma unroll
            for (int s = 0; s < 8; s++) {
                const int kk = warp * 64 + s * 8;
                unsigned af[NB / 16][4];
#pragma unroll
                for (int mi = 0; mi < NB / 16; mi++)
                    ldsm4(af[mi][0], af[mi][1], af[mi][2], af[mi][3],
                          &Hs[mi * 16 + arow][kk + akadd]);
#pragma unroll
                for (int mi = 0; mi < NB / 16; mi++)
#pragma unroll
                    for (int ni = 0; ni < 4; ni++)
                        mma_tf32(acc[mi][ni], af[mi], bfr[s][ni]);
            }
        }

        // write partials
        {
            float* zs = zslab + warp * NB * ZP;
#pragma unroll
            for (int mi = 0; mi < NB / 16; mi++)
#pragma unroll
                for (int ni = 0; ni < 4; ni++) {
                    const int r = mi * 16, c = ni * 8 + 2 * t;
                    float2 v0; v0.x = acc[mi][ni][0]; v0.y = acc[mi][ni][1];
                    float2 v1; v1.x = acc[mi][ni][2]; v1.y = acc[mi][ni][3];
                    *(float2*)&zs[(size_t)(r + g)     * ZP + c] = v0;
                    *(float2*)&zs[(size_t)(r + g + 8) * ZP + c] = v1;
                }
        }
        __syncthreads();

        // reduce 8 warps + gates + h store (1 unit per active thread)
        if (gact) {
            float z[4];
#pragma unroll
            for (int gate = 0; gate < 4; gate++) {
                const int cidx = gate * 8 + guu;
                float s = 0.f;
#pragma unroll
                for (int w = 0; w < 8; w++)
                    s += zslab[((size_t)w * NB + gb) * ZP + cidx];
                z[gate] = s + xwv[gate];
            }
            const float si = sigm(z[0]), sf = sigm(z[1]), so = sigm(z[3]);
            const float gr = fmaxf(z[2], 0.f);
            const float cn = sf * c_reg + si * gr;
            c_reg = cn;
            const float hv = so * fmaxf(cn, 0.f);
            const size_t idx = ((size_t)(bbase + gb) * TT + tout) * DD + u0 + guu;
            seqt[idx] = f2tf(hv);
            if (seqf) seqf[idx] = hv;

            // prefetch xw for next step (before signal / next wait)
            if (st + 1 < TT) {
                const int tnext = rev ? (tout - 1) : (tout + 1);
                const size_t xrow = ((size_t)(bbase + gb) * TT + tnext) * GG;
#pragma unroll
                for (int gate = 0; gate < 4; gate++)
                    xwv[gate] = xw[xrow + (size_t)gate * DD + u0 + guu];
            }
        }

        if (st < TT - 1) bar_signal(myflag, (unsigned)(st + 1));
    }
}

#define SMEM_REC1 ((16*HW + 8*16*ZP) * 4)    // 53504
#define SMEM_REC2 ((32*HW + 8*32*ZP) * 4)    // 107008

// layer 1: 256 blocks = 4 batch-groups(16) x 64 col-groups(8 units)
__global__ void __launch_bounds__(256, 2) k_rec1(
    const float* __restrict__ xw, const float* __restrict__ U,
    unsigned* __restrict__ seqt)
{
    const int bx = blockIdx.x;
    const int bg = bx & 3, cg = bx >> 2;
    rec_engine<16>(xw, U, (float*)0, seqt, bg * 16, cg * 8, false,
                   &g_flags1[bg][cg * 8], &g_flags1[bg][0]);
}

// layer 2: 256 blocks = dir(2) x bg(2, 32 batches) x 64 col-groups
__global__ void __launch_bounds__(256, 2) k_rec2(
    const float* __restrict__ xwf, const float* __restrict__ Uf,
    float* __restrict__ hf, unsigned* __restrict__ hft,
    const float* __restrict__ xwb, const float* __restrict__ Ub,
    float* __restrict__ hb, unsigned* __restrict__ hbt)
{
    const int bx  = blockIdx.x;
    const int dir = bx >> 7;
    const int bg2 = (bx >> 6) & 1, cg = bx & 63;
    const int grp = dir * 2 + bg2;
    if (dir == 0)
        rec_engine<32>(xwf, Uf, hf, hft, bg2 * 32, cg * 8, false,
                       &g_flags2[grp][cg * 8], &g_flags2[grp][0]);
    else
        rec_engine<32>(xwb, Ub, hb, hbt, bg2 * 32, cg * 8, true,
                       &g_flags2[grp][cg * 8], &g_flags2[grp][0]);
}

// ---------------- LayerNorm(concat(hf,hb)) * gamma + beta + residual --------
__global__ void __launch_bounds__(256) k_ln_residual(
    const float* __restrict__ x, const float* __restrict__ gamma,
    const float* __restrict__ beta, const float* __restrict__ hf,
    const float* __restrict__ hb, float* __restrict__ out)
{
    const int bt  = blockIdx.x;
    const int tid = threadIdx.x;
    const float* hfr = hf + (size_t)bt * DD;
    const float* hbr = hb + (size_t)bt * DD;

    float v[4];
    float s = 0.f;
#pragma unroll
    for (int r = 0; r < 4; r++) {
        int i = tid + r * 256;
        float val = (i < DD) ? hfr[i] : hbr[i - DD];
        v[r] = val; s += val;
    }

    __shared__ float rbuf[8];
    __shared__ float stat[2];
    const int lane = tid & 31, w = tid >> 5;
#pragma unroll
    for (int o = 16; o; o >>= 1) s += __shfl_xor_sync(0xffffffffu, s, o);
    if (lane == 0) rbuf[w] = s;
    __syncthreads();
    if (tid == 0) {
        float tsum = 0.f;
        for (int i = 0; i < 8; i++) tsum += rbuf[i];
        stat[0] = tsum * (1.f / 1024.f);
    }
    __syncthreads();
    const float mean = stat[0];

    float s2 = 0.f;
#pragma unroll
    for (int r = 0; r < 4; r++) { float d = v[r] - mean; s2 += d * d; }
#pragma unroll
    for (int o = 16; o; o >>= 1) s2 += __shfl_xor_sync(0xffffffffu, s2, o);
    if (lane == 0) rbuf[w] = s2;
    __syncthreads();
    if (tid == 0) {
        float tsum = 0.f;
        for (int i = 0; i < 8; i++) tsum += rbuf[i];
        stat[1] = rsqrtf(tsum * (1.f / 1024.f) + 1e-6f);
    }
    __syncthreads();
    const float rstd = stat[1];

    const float* xr  = x   + (size_t)bt * II;
    float*       otr = out + (size_t)bt * II;
#pragma unroll
    for (int r = 0; r < 4; r++) {
        int i = tid + r * 256;
        otr[i] = xr[i] + (v[r] - mean) * rstd * gamma[i] + beta[i];
    }
}

// ---------------- launcher ---------------------------------------------------
extern "C" void kernel_launch(void* const* d_in, const int* in_sizes, int n_in,
                              void* d_out, int out_size)
{
    (void)in_sizes; (void)n_in; (void)out_size;
    const float* x     = (const float*)d_in[0];
    const float* W1    = (const float*)d_in[1];
    const float* U1    = (const float*)d_in[2];
    const float* b1    = (const float*)d_in[3];
    const float* Wf    = (const float*)d_in[4];
    const float* Uf    = (const float*)d_in[5];
    const float* bf    = (const float*)d_in[6];
    const float* Wb    = (const float*)d_in[7];
    const float* Ub    = (const float*)d_in[8];
    const float* bb    = (const float*)d_in[9];
    const float* gamma = (const float*)d_in[10];
    const float* beta  = (const float*)d_in[11];
    float* out = (float*)d_out;

    float *xw1, *xwf, *xwb, *hf, *hb;
    unsigned *h1t, *hft, *hbt;
    cudaGetSymbolAddress((void**)&xw1, g_xw1);
    cudaGetSymbolAddress((void**)&xwf, g_xwf);
    cudaGetSymbolAddress((void**)&xwb, g_xwb);
    cudaGetSymbolAddress((void**)&h1t, g_h1t);
    cudaGetSymbolAddress((void**)&hf,  g_hf);
    cudaGetSymbolAddress((void**)&hb,  g_hb);
    cudaGetSymbolAddress((void**)&hft, g_hft);
    cudaGetSymbolAddress((void**)&hbt, g_hbt);

    cudaFuncSetAttribute(k_rec1, cudaFuncAttributeMaxDynamicSharedMemorySize, SMEM_REC1);
    cudaFuncSetAttribute(k_rec2, cudaFuncAttributeMaxDynamicSharedMemorySize, SMEM_REC2);

    dim3 ggrid(GG / 128, BT / 128);   // (16, 256)

    k_zero_flags<<<16, 256>>>();
    k_mma_gemm<false><<<ggrid, 256>>>(x, W1, b1, xw1, II);
    k_rec1<<<256, 256, SMEM_REC1>>>(xw1, U1, h1t);
    k_mma_gemm<true><<<ggrid, 256>>>((const float*)h1t, Wf, bf, xwf, DD);
    k_mma_gemm<true><<<ggrid, 256>>>((const float*)h1t, Wb, bb, xwb, DD);
    k_rec2<<<256, 256, SMEM_REC2>>>(xwf, Uf, hf, hft, xwb, Ub, hb, hbt);
    k_ln_residual<<<BT, 256>>>(x, gamma, beta, hf, hb, out);
}